// round 11
// baseline (speedup 1.0000x reference)
#include <cuda_runtime.h>
#include <cstdint>

#define Bz 8
#define C  512
#define NH 8
#define HD 64
#define N  1024   /* 32*32 */
#define SMSCALE 0.18033688011112042f   /* 0.125 * log2(e) */

// Scratch: q/k/v (b,h,n,d) and attention output TRANSPOSED (b,c,n).
// All hold tf32-pre-rounded fp32 bit patterns (consumed only by tf32 MMA).
__device__ float g_q[Bz*NH*N*HD];
__device__ float g_k[Bz*NH*N*HD];
__device__ float g_v[Bz*NH*N*HD];
__device__ float g_ao[Bz*C*N];
// Pre-rounded inputs (same layouts as the originals).
__device__ float g_xr [Bz*C*N];
__device__ float g_wqr[3*C*C];
__device__ float g_wpr[C*C];

// ---------------------------------------------------------------------------
__device__ __forceinline__ uint32_t f2tf(float f) {
    uint32_t r;
    asm("cvt.rna.tf32.f32 %0, %1;" : "=r"(r) : "f"(f));
    return r;
}
__device__ __forceinline__ float rnd(float f) { return __uint_as_float(f2tf(f)); }
__device__ __forceinline__ float ex2(float x) {
    float r;
    asm("ex2.approx.ftz.f32 %0, %1;" : "=f"(r) : "f"(x));
    return r;
}
__device__ __forceinline__ void mma8(float* c, const uint32_t* a, const uint32_t* b) {
    asm volatile(
        "mma.sync.aligned.m16n8k8.row.col.f32.tf32.tf32.f32 "
        "{%0,%1,%2,%3}, {%4,%5,%6,%7}, {%8,%9}, {%0,%1,%2,%3};"
        : "+f"(c[0]), "+f"(c[1]), "+f"(c[2]), "+f"(c[3])
        : "r"(a[0]), "r"(a[1]), "r"(a[2]), "r"(a[3]), "r"(b[0]), "r"(b[1]));
}
__device__ __forceinline__ void cp16(uint32_t d, const void* s) {
    asm volatile("cp.async.cg.shared.global [%0], [%1], 16;" :: "r"(d), "l"(s));
}
__device__ __forceinline__ void cp_commit() { asm volatile("cp.async.commit_group;"); }
template<int NG> __device__ __forceinline__ void waitg() {
    asm volatile("cp.async.wait_group %0;" :: "n"(NG));
}

extern __shared__ uint32_t sm_u[];

// Stage sizes (words) for the GEMM pipelines.
#define A_ST 2176   /* 16 * 136 */
#define B_ST 2560   /* 128 * 20 */
#define QP_SMEM ((A_ST + B_ST) * 4 * 4)   /* 4 stages -> 75,776 B */

// ---------------------------------------------------------------------------
// Prepass: elementwise tf32 round into a __device__ global selected in DEVICE
// code (host code must never take the address of a __device__ symbol).
__global__ __launch_bounds__(256) void round_kernel(const float4* __restrict__ src,
                                                    int which) {
    float4* dst = (which == 0) ? (float4*)g_xr
                : (which == 1) ? (float4*)g_wqr
                               : (float4*)g_wpr;
    int i = blockIdx.x * 256 + threadIdx.x;
    float4 v = src[i];
    v.x = rnd(v.x); v.y = rnd(v.y); v.z = rnd(v.z); v.w = rnd(v.w);
    dst[i] = v;
}

// ---------------------------------------------------------------------------
// Kernel 1: qkv = x_seq @ W_qkv^T + b_qkv.  Block tile 128(m) x 128(o), BK=16,
// 4-stage cp.async pipeline (wait_group 2 steady state). A smem [k][m] stride
// 136; B smem natural [o][k] stride 20. Zero cvts in the mainloop.
// ---------------------------------------------------------------------------
__global__ __launch_bounds__(256) void qkv_kernel(const float* __restrict__ bqkv) {
    uint32_t* As = sm_u;                 // 4 x A_ST
    uint32_t* Bs = sm_u + 4 * A_ST;      // 4 x B_ST
    const int b  = blockIdx.z;
    const int n0 = blockIdx.x * 128;
    const int o0 = blockIdx.y * 128;
    const int t = threadIdx.x, w = t >> 5, lane = t & 31;
    const int g = lane >> 2, tg = lane & 3;
    const int wm = w & 1, wn = w >> 1;
    const float* xb = g_xr + (size_t)b * C * N;
    const uint32_t asb = (uint32_t)__cvta_generic_to_shared(As);
    const uint32_t bsb = (uint32_t)__cvta_generic_to_shared(Bs);

    float acc[4][4][4] = {};

    auto load_stage = [&](int i) {
        const int k0 = i * 16, buf = i & 3;
        const uint32_t ab = asb + buf * (A_ST * 4);
        const uint32_t bb = bsb + buf * (B_ST * 4);
        #pragma unroll
        for (int s = 0; s < 2; s++) {
            int idx = t + s * 256;
            int kk = idx >> 5, col = (idx & 31) * 4;
            cp16(ab + (kk * 136 + col) * 4, xb + (size_t)(k0 + kk) * N + n0 + col);
        }
        #pragma unroll
        for (int s = 0; s < 2; s++) {
            int idx = t + s * 256;
            int oo = idx >> 2, k4 = (idx & 3) * 4;
            cp16(bb + (oo * 20 + k4) * 4, g_wqr + (size_t)(o0 + oo) * C + k0 + k4);
        }
    };

    load_stage(0); cp_commit();
    load_stage(1); cp_commit();
    load_stage(2); cp_commit();
    for (int i = 0; i < 32; i++) {
        if (i <= 29) waitg<2>(); else if (i == 30) waitg<1>(); else waitg<0>();
        __syncthreads();
        if (i + 3 < 32) { load_stage(i + 3); cp_commit(); }
        const uint32_t* Ab = As + (i & 3) * A_ST;
        const uint32_t* Bb = Bs + (i & 3) * B_ST;
        #pragma unroll
        for (int ks = 0; ks < 2; ks++) {
            const int kk = ks * 8;
            uint32_t a[4][4], bv[4][2];
            #pragma unroll
            for (int ii = 0; ii < 4; ii++) {
                const uint32_t* p = &Ab[(kk + tg) * 136 + wm * 64 + ii * 16 + g];
                a[ii][0] = p[0];       a[ii][1] = p[8];
                a[ii][2] = p[4 * 136]; a[ii][3] = p[4 * 136 + 8];
            }
            #pragma unroll
            for (int j = 0; j < 4; j++) {
                const uint32_t* p = &Bb[(wn * 32 + j * 8 + g) * 20 + kk + tg];
                bv[j][0] = p[0]; bv[j][1] = p[4];
            }
            #pragma unroll
            for (int ii = 0; ii < 4; ii++)
                #pragma unroll
                for (int j = 0; j < 4; j++) mma8(acc[ii][j], a[ii], bv[j]);
        }
    }

    // Epilogue: scatter tf32-rounded q/k/v (b,h,n,d).
    const int three = o0 >> 9;
    float* base = (three == 0 ? g_q : (three == 1 ? g_k : g_v));
    #pragma unroll
    for (int j = 0; j < 4; j++) {
        const int o = o0 + wn * 32 + j * 8 + 2 * tg;
        const int h = (o >> 6) & 7, d = o & 63;
        const float b0v = bqkv[o], b1v = bqkv[o + 1];
        float* dsth = base + ((size_t)(b * NH + h) * N) * HD + d;
        #pragma unroll
        for (int i = 0; i < 4; i++) {
            const int n1 = n0 + wm * 64 + i * 16 + g;
            float2 v0 = {rnd(acc[i][j][0] + b0v), rnd(acc[i][j][1] + b1v)};
            float2 v1 = {rnd(acc[i][j][2] + b0v), rnd(acc[i][j][3] + b1v)};
            *(float2*)&dsth[(size_t)n1 * HD]       = v0;
            *(float2*)&dsth[(size_t)(n1 + 8) * HD] = v1;
        }
    }
}

// ---------------------------------------------------------------------------
// Kernel 2: causal flash attention. 8 warps, 128 q-rows per block, 64-wide KV
// tiles (double-buffered cp.async). Per-warp code identical to the known-good
// 4-warp version (16 rows/warp); masks in global coordinates; warps skip
// tiles fully above their rows (zero contribution, bit-identical).
// ---------------------------------------------------------------------------
#define AT_SMEM ((128*68 + 2*64*68 + 2*64*72 + 128*68) * 4)   /* 141,312 B */

__global__ __launch_bounds__(256) void attn_kernel() {
    uint32_t* Qs = sm_u;                 // [128][68]
    uint32_t* Ks = Qs + 128 * 68;        // 2 x [64][68] natural [kpos][d]
    uint32_t* Vs = Ks + 2 * 64 * 68;     // 2 x [64][72] natural [kpos][d]
    uint32_t* Sf = Vs + 2 * 64 * 72;     // [128][68] P (tf32), warp-private rows

    const int qb = 7 - (int)blockIdx.x;  // heavy blocks first
    const int bh = blockIdx.y;
    const int n0 = qb * 128;
    const float* Q = g_q + (size_t)bh * N * HD;
    const float* K = g_k + (size_t)bh * N * HD;
    const float* V = g_v + (size_t)bh * N * HD;

    const int t = threadIdx.x, w = t >> 5, lane = t & 31;
    const int g = lane >> 2, tg = lane & 3;
    const int m0 = w * 16;
    const int row0 = n0 + m0;            // warp's first global row
    const uint32_t qsb = (uint32_t)__cvta_generic_to_shared(Qs);
    const uint32_t ksb = (uint32_t)__cvta_generic_to_shared(Ks);
    const uint32_t vsb = (uint32_t)__cvta_generic_to_shared(Vs);

    #pragma unroll
    for (int it = 0; it < 8; it++) {     // 128 rows x 64 cols
        int idx = t + it * 256;
        int row = idx >> 4, col = (idx & 15) * 4;
        cp16(qsb + (row * 68 + col) * 4, Q + (size_t)(n0 + row) * HD + col);
    }
    auto load_kv = [&](int kt) {
        const int k0 = kt * 64, buf = kt & 1;
        #pragma unroll
        for (int it = 0; it < 4; it++) { // 64 rows x 64 cols each
            int idx = t + it * 256;
            int row = idx >> 4, col = (idx & 15) * 4;
            cp16(ksb + (buf * (64 * 68) + row * 68 + col) * 4, K + (size_t)(k0 + row) * HD + col);
            cp16(vsb + (buf * (64 * 72) + row * 72 + col) * 4, V + (size_t)(k0 + row) * HD + col);
        }
    };
    load_kv(0); cp_commit();

    float mr0 = -1e30f, mr1 = -1e30f, l0 = 0.f, l1 = 0.f;
    float o[8][4] = {};
    const int ktmax = 2 * qb + 1;

    for (int kt = 0; kt <= ktmax; kt++) {
        waitg<0>(); __syncthreads();
        if (kt < ktmax) { load_kv(kt + 1); cp_commit(); }
        const int k0 = kt * 64;
        if (k0 > row0 + 15) continue;    // tile fully above this warp's rows
        const uint32_t* kb = Ks + (kt & 1) * (64 * 68);
        const uint32_t* vb = Vs + (kt & 1) * (64 * 72);

        // ---- Phase 1: S = Q K^T ----
        float s[8][4] = {};
        #pragma unroll
        for (int ks = 0; ks < 8; ks++) {
            const int kk = ks * 8;
            uint32_t a[4];
            const uint32_t* pa = &Qs[(m0 + g) * 68 + kk + tg];
            a[0] = pa[0]; a[1] = pa[8 * 68]; a[2] = pa[4]; a[3] = pa[8 * 68 + 4];
            #pragma unroll
            for (int j = 0; j < 8; j++) {
                uint32_t bb2[2];
                const uint32_t* pb = &kb[(j * 8 + g) * 68 + kk + tg];
                bb2[0] = pb[0]; bb2[1] = pb[4];
                mma8(s[j], a, bb2);
            }
        }

        if (k0 + 63 > row0) {            // tile crosses the diagonal for this warp
            #pragma unroll
            for (int j = 0; j < 8; j++) {
                const int c0 = k0 + j * 8 + 2 * tg;      // global col
                const int r0g = row0 + g, r1g = row0 + g + 8;
                if (c0     > r0g) s[j][0] = -1e30f;
                if (c0 + 1 > r0g) s[j][1] = -1e30f;
                if (c0     > r1g) s[j][2] = -1e30f;
                if (c0 + 1 > r1g) s[j][3] = -1e30f;
            }
        }

        // ---- softmax in registers (quad owns rows g, g+8) ----
        float mx0 = -1e30f, mx1 = -1e30f;
        #pragma unroll
        for (int j = 0; j < 8; j++) {
            mx0 = fmaxf(mx0, fmaxf(s[j][0], s[j][1]));
            mx1 = fmaxf(mx1, fmaxf(s[j][2], s[j][3]));
        }
        mx0 = fmaxf(mx0, __shfl_xor_sync(0xffffffffu, mx0, 1));
        mx0 = fmaxf(mx0, __shfl_xor_sync(0xffffffffu, mx0, 2));
        mx1 = fmaxf(mx1, __shfl_xor_sync(0xffffffffu, mx1, 1));
        mx1 = fmaxf(mx1, __shfl_xor_sync(0xffffffffu, mx1, 2));
        const float mn0 = fmaxf(mr0, mx0 * SMSCALE);
        const float mn1 = fmaxf(mr1, mx1 * SMSCALE);
        const float f0 = ex2(mr0 - mn0), f1 = ex2(mr1 - mn1);
        mr0 = mn0; mr1 = mn1;

        float sum0 = 0.f, sum1 = 0.f;
        uint32_t* sp0 = &Sf[(m0 + g) * 68 + 2 * tg];
        uint32_t* sp1 = sp0 + 8 * 68;
        #pragma unroll
        for (int j = 0; j < 8; j++) {
            float p0 = ex2(s[j][0] * SMSCALE - mn0);
            float p1 = ex2(s[j][1] * SMSCALE - mn0);
            float p2 = ex2(s[j][2] * SMSCALE - mn1);
            float p3 = ex2(s[j][3] * SMSCALE - mn1);
            sum0 += p0 + p1; sum1 += p2 + p3;
            sp0[j * 8] = f2tf(p0); sp0[j * 8 + 1] = f2tf(p1);
            sp1[j * 8] = f2tf(p2); sp1[j * 8 + 1] = f2tf(p3);
        }
        sum0 += __shfl_xor_sync(0xffffffffu, sum0, 1);
        sum0 += __shfl_xor_sync(0xffffffffu, sum0, 2);
        sum1 += __shfl_xor_sync(0xffffffffu, sum1, 1);
        sum1 += __shfl_xor_sync(0xffffffffu, sum1, 2);
        l0 = l0 * f0 + sum0;
        l1 = l1 * f1 + sum1;
        __syncwarp();

        #pragma unroll
        for (int j = 0; j < 8; j++) {
            o[j][0] *= f0; o[j][1] *= f0; o[j][2] *= f1; o[j][3] *= f1;
        }
        // ---- Phase 2: O += P V ----
        #pragma unroll
        for (int ks = 0; ks < 8; ks++) {
            const int kk = ks * 8;
            uint32_t a[4];
            const uint32_t* pa = &Sf[(m0 + g) * 68 + kk + tg];
            a[0] = pa[0]; a[1] = pa[8 * 68]; a[2] = pa[4]; a[3] = pa[8 * 68 + 4];
            #pragma unroll
            for (int j = 0; j < 8; j++) {
                uint32_t bb2[2];
                const uint32_t* pb = &vb[(kk + tg) * 72 + j * 8 + g];
                bb2[0] = pb[0]; bb2[1] = pb[4 * 72];
                mma8(o[j], a, bb2);
            }
        }
    }

    // Epilogue: write aoT [b][cfeat][n], tf32-rounded (feeds proj tf32 MMA).
    const float inv0 = 1.f / l0, inv1 = 1.f / l1;
    const int b = bh >> 3, h = bh & 7;
    float* ao = g_ao + (size_t)b * C * N + (size_t)h * 64 * N;
    const int n1 = n0 + m0 + g;
    #pragma unroll
    for (int j = 0; j < 8; j++) {
        const int d = j * 8 + 2 * tg;
        ao[(size_t)d * N + n1]           = rnd(o[j][0] * inv0);
        ao[(size_t)(d + 1) * N + n1]     = rnd(o[j][1] * inv0);
        ao[(size_t)d * N + n1 + 8]       = rnd(o[j][2] * inv1);
        ao[(size_t)(d + 1) * N + n1 + 8] = rnd(o[j][3] * inv1);
    }
}

// ---------------------------------------------------------------------------
// Kernel 3: out[b][co][n] = aoT[b][:,n] @ W_proj[co][:] + b_proj[co].
// Same 4-stage pipeline as qkv; both operands pre-rounded -> zero cvts.
// ---------------------------------------------------------------------------
__global__ __launch_bounds__(256) void proj_kernel(const float* __restrict__ bp,
                                                   float* __restrict__ out) {
    uint32_t* As = sm_u;
    uint32_t* Bs = sm_u + 4 * A_ST;
    const int b  = blockIdx.z;
    const int n0 = blockIdx.x * 128;
    const int c0 = blockIdx.y * 128;
    const int t = threadIdx.x, w = t >> 5, lane = t & 31;
    const int g = lane >> 2, tg = lane & 3;
    const int wm = w & 1, wn = w >> 1;
    const float* A = g_ao + (size_t)b * C * N;
    const uint32_t asb = (uint32_t)__cvta_generic_to_shared(As);
    const uint32_t bsb = (uint32_t)__cvta_generic_to_shared(Bs);

    float acc[4][4][4] = {};

    auto load_stage = [&](int i) {
        const int k0 = i * 16, buf = i & 3;
        const uint32_t ab = asb + buf * (A_ST * 4);
        const uint32_t bb = bsb + buf * (B_ST * 4);
        #pragma unroll
        for (int s = 0; s < 2; s++) {
            int idx = t + s * 256;
            int kk = idx >> 5, col = (idx & 31) * 4;
            cp16(ab + (kk * 136 + col) * 4, A + (size_t)(k0 + kk) * N + n0 + col);
        }
        #pragma unroll
        for (int s = 0; s < 2; s++) {
            int idx = t + s * 256;
            int oo = idx >> 2, k4 = (idx & 3) * 4;
            cp16(bb + (oo * 20 + k4) * 4, g_wpr + (size_t)(c0 + oo) * C + k0 + k4);
        }
    };

    load_stage(0); cp_commit();
    load_stage(1); cp_commit();
    load_stage(2); cp_commit();
    for (int i = 0; i < 32; i++) {
        if (i <= 29) waitg<2>(); else if (i == 30) waitg<1>(); else waitg<0>();
        __syncthreads();
        if (i + 3 < 32) { load_stage(i + 3); cp_commit(); }
        const uint32_t* Ab = As + (i & 3) * A_ST;
        const uint32_t* Bb = Bs + (i & 3) * B_ST;
        #pragma unroll
        for (int ks = 0; ks < 2; ks++) {
            const int kk = ks * 8;
            uint32_t a[4][4], bv[4][2];
            #pragma unroll
            for (int ii = 0; ii < 4; ii++) {
                const uint32_t* p = &Ab[(kk + tg) * 136 + wm * 64 + ii * 16 + g];
                a[ii][0] = p[0];       a[ii][1] = p[8];
                a[ii][2] = p[4 * 136]; a[ii][3] = p[4 * 136 + 8];
            }
            #pragma unroll
            for (int j = 0; j < 4; j++) {
                const uint32_t* p = &Bb[(wn * 32 + j * 8 + g) * 20 + kk + tg];
                bv[j][0] = p[0]; bv[j][1] = p[4];
            }
            #pragma unroll
            for (int ii = 0; ii < 4; ii++)
                #pragma unroll
                for (int j = 0; j < 4; j++) mma8(acc[ii][j], a[ii], bv[j]);
        }
    }

    #pragma unroll
    for (int j = 0; j < 4; j++) {
        const int co = c0 + wn * 32 + j * 8 + 2 * tg;
        const float b0v = bp[co], b1v = bp[co + 1];
        float* r0 = out + ((size_t)b * C + co) * N;
        float* r1 = out + ((size_t)b * C + co + 1) * N;
        #pragma unroll
        for (int i = 0; i < 4; i++) {
            const int n1 = n0 + wm * 64 + i * 16 + g;
            r0[n1]     = acc[i][j][0] + b0v;
            r1[n1]     = acc[i][j][1] + b1v;
            r0[n1 + 8] = acc[i][j][2] + b0v;
            r1[n1 + 8] = acc[i][j][3] + b1v;
        }
    }
}

// ---------------------------------------------------------------------------
extern "C" void kernel_launch(void* const* d_in, const int* in_sizes, int n_in,
                              void* d_out, int out_size) {
    (void)in_sizes; (void)n_in; (void)out_size;
    const float* x    = (const float*)d_in[0];
    const float* Wqkv = (const float*)d_in[1];
    const float* bqkv = (const float*)d_in[2];
    const float* Wp   = (const float*)d_in[3];
    const float* bp   = (const float*)d_in[4];
    float* out = (float*)d_out;

    cudaFuncSetAttribute(qkv_kernel,
                         cudaFuncAttributeMaxDynamicSharedMemorySize, QP_SMEM);
    cudaFuncSetAttribute(proj_kernel,
                         cudaFuncAttributeMaxDynamicSharedMemorySize, QP_SMEM);
    cudaFuncSetAttribute(attn_kernel,
                         cudaFuncAttributeMaxDynamicSharedMemorySize, AT_SMEM);

    round_kernel<<<Bz * C * N / 4 / 256, 256>>>((const float4*)x, 0);
    round_kernel<<<3 * C * C / 4 / 256, 256>>>((const float4*)Wqkv, 1);
    round_kernel<<<C * C / 4 / 256, 256>>>((const float4*)Wp, 2);
    qkv_kernel<<<dim3(8, 12, Bz), 256, QP_SMEM>>>(bqkv);
    attn_kernel<<<dim3(8, 64), 256, AT_SMEM>>>();
    proj_kernel<<<dim3(8, 4, Bz), 256, QP_SMEM>>>(bp, out);
}